// round 12
// baseline (speedup 1.0000x reference)
#include <cuda_runtime.h>
#include <cuda_fp16.h>
#include <math_constants.h>
#include <cstdint>

#define DIM 128
#define KCODES 2048
#define NROWS 65536
#define NZ (NROWS * DIM)
#define TILE_M 128
#define CHUNK 64
#define CHUNKS 32
#define NTH 256

__device__ __align__(16) float g_t[KCODES];
__device__ int   g_idx[NROWS];
__device__ float g_part[1024];
__device__ __align__(16) __half g_bh[KCODES * DIM];   // fl16(2048*e)
__device__ int g_cntA, g_cntB;
__device__ __align__(16) int4 g_listA[NROWS];
__device__ int g_listB[NROWS];

// ---- smem byte offsets (stage 1): 109568 B -> 2 CTAs/SM ----
#define OFF_A    0          // 128 rows x 256B (f16 z) = 32768
#define OFF_B    32768      // 4 buffers x 16384
#define BUFSZ    16384
#define OFF_TALL 98304      // 2048 f32
#define OFF_SROW 106496     // 128 f32
#define OFF_V0A  107008
#define OFF_I0A  107520
#define OFF_V1A  108032
#define OFF_I1A  108544
#define OFF_V2A  109056
#define SMEM_SZ  109568

// ---- PTX helpers ----
static __device__ __forceinline__ void ldsm4(uint32_t* r, uint32_t a) {
    asm volatile("ldmatrix.sync.aligned.m8n8.x4.shared.b16 {%0,%1,%2,%3}, [%4];"
                 : "=r"(r[0]), "=r"(r[1]), "=r"(r[2]), "=r"(r[3]) : "r"(a));
}
static __device__ __forceinline__ void mma16816(float* c, const uint32_t* a,
                                                uint32_t b0, uint32_t b1) {
    asm volatile("mma.sync.aligned.m16n8k16.row.col.f32.f16.f16.f32 "
                 "{%0,%1,%2,%3}, {%4,%5,%6,%7}, {%8,%9}, {%0,%1,%2,%3};"
                 : "+f"(c[0]), "+f"(c[1]), "+f"(c[2]), "+f"(c[3])
                 : "r"(a[0]), "r"(a[1]), "r"(a[2]), "r"(a[3]), "r"(b0), "r"(b1));
}
#define CP_ASYNC16(d, s) asm volatile("cp.async.ca.shared.global [%0], [%1], 16;" :: "r"(d), "l"(s))
#define CP_COMMIT() asm volatile("cp.async.commit_group;" ::: "memory")
#define CP_WAIT0()  asm volatile("cp.async.wait_group 0;" ::: "memory")
#define CP_WAIT1()  asm volatile("cp.async.wait_group 1;" ::: "memory")
#define CP_WAIT2()  asm volatile("cp.async.wait_group 2;" ::: "memory")

// 3rd smallest value of two sorted triples (values only; ties fine)
static __device__ __forceinline__ float third3(float a0, float a1, float a2,
                                               float b0, float b1, float b2) {
    if (a0 <= b0) {
        if (a1 <= b0) return fminf(a2, b0);
        return fminf(a1, b1);
    } else {
        if (b1 <= a0) return fminf(b2, a0);
        return fminf(a1, b1);
    }
}

// ---- prep: ||e||^2, exact sequential fp32, coalesced; zero counters ----
__global__ __launch_bounds__(128)
void k_embnorm(const float* __restrict__ emb) {
    __shared__ float sm[128 * 33];
    const int tid = threadIdx.x;
    const int cb = blockIdx.x * 128;
    if (blockIdx.x == 0 && tid == 0) { g_cntA = 0; g_cntB = 0; }
    float s = 0.f;
    for (int kc = 0; kc < 4; ++kc) {
        __syncthreads();
        for (int i = tid; i < 128 * 32; i += 128) {
            int cl = i >> 5, kk = i & 31;
            sm[cl * 33 + kk] = emb[(size_t)(cb + cl) * DIM + kc * 32 + kk];
        }
        __syncthreads();
        #pragma unroll 8
        for (int kk = 0; kk < 32; ++kk) {
            float v = sm[tid * 33 + kk];
            s = __fadd_rn(s, __fmul_rn(v, v));
        }
    }
    g_t[cb + tid] = s;
}

// ---- prep: f16 codebook scaled by 2048 ----
__global__ void k_split(const float* __restrict__ emb) {
    int idx = blockIdx.x * blockDim.x + threadIdx.x;
    g_bh[idx] = __float2half_rn(__fmul_rn(emb[idx], 2048.0f));
}

// ---- B-chunk async fill ----
static __device__ __forceinline__ void fill_async(uint32_t bBase, int chunk, int tid) {
    const char* src = (const char*)g_bh + (size_t)chunk * CHUNK * 256;
    #pragma unroll
    for (int j = 0; j < 4; ++j) {
        int i = tid + j * NTH;
        int code = i >> 4;
        int kg = i & 15;
        uint32_t d = bBase + (uint32_t)(code * 256 + (((kg & ~7) | ((kg ^ code) & 7)) << 4));
        CP_ASYNC16(d, src + code * 256 + kg * 16);
    }
    CP_COMMIT();
}

// ---- stage 1: f16 HMMA GEMM + top-3 tracking + classification ----
__global__ __launch_bounds__(NTH, 2)
void k_argmin_tc(const float* __restrict__ z) {
    extern __shared__ char smc[];
    uint32_t sb;
    asm("{ .reg .u64 t; cvta.to.shared.u64 t, %1; cvt.u32.u64 %0, t; }" : "=r"(sb) : "l"(smc));
    float* tall = (float*)(smc + OFF_TALL);
    float* srow = (float*)(smc + OFF_SROW);
    float* V0A  = (float*)(smc + OFF_V0A);
    int*   I0A  = (int*)(smc + OFF_I0A);
    float* V1A  = (float*)(smc + OFF_V1A);
    int*   I1A  = (int*)(smc + OFF_I1A);
    float* V2A  = (float*)(smc + OFF_V2A);

    const int tid = threadIdx.x;
    const int lane = tid & 31, wid = tid >> 5;
    const int wm = wid & 3, wn = wid >> 2;
    const int rbase = blockIdx.x * TILE_M;

    fill_async(sb + OFF_B + 0 * BUFSZ, 0, tid);
    fill_async(sb + OFF_B + 1 * BUFSZ, 1, tid);
    fill_async(sb + OFF_B + 2 * BUFSZ, 2, tid);

    for (int i = tid; i < KCODES / 4; i += NTH)
        ((float4*)tall)[i] = ((const float4*)g_t)[i];

    // A tile (f16 z), 256B/row, XOR-swizzled
    {
        int r = tid >> 1, half = tid & 1;
        const float* zr = z + (size_t)(rbase + r) * DIM + half * 64;
        char* arow = smc + OFF_A + r * 256;
        int rx = r & 7;
        #pragma unroll
        for (int g = 0; g < 8; ++g) {
            float4 v0 = *(const float4*)(zr + g * 8);
            float4 v1 = *(const float4*)(zr + g * 8 + 4);
            float f[8] = {v0.x, v0.y, v0.z, v0.w, v1.x, v1.y, v1.z, v1.w};
            uint32_t hp[4];
            #pragma unroll
            for (int e = 0; e < 4; ++e) {
                __half a = __float2half_rn(f[2 * e]);
                __half b = __float2half_rn(f[2 * e + 1]);
                hp[e] = (uint32_t)__half_as_ushort(a) | ((uint32_t)__half_as_ushort(b) << 16);
            }
            int kg0 = half * 8 + g;
            int ks0 = (kg0 & ~7) | ((kg0 & 7) ^ rx);
            *(uint4*)(arow + ks0 * 16) = *(uint4*)hp;
        }
    }

    if (tid < TILE_M) {
        const float* zr = z + (size_t)(rbase + tid) * DIM;
        float s = 0.f;
        #pragma unroll 8
        for (int k = 0; k < DIM; ++k)
            s = __fadd_rn(s, __fmul_rn(zr[k], zr[k]));
        srow[tid] = s;
    }
    __syncthreads();

    const int rx7 = lane & 7;
    const int klane = (lane >> 4) & 1;
    const uint32_t aRow0 = sb + OFF_A +
        (uint32_t)((wm * 32 + (lane & 7) + ((lane & 8) ? 8 : 0)) * 256);
    const uint32_t bRowOff =
        (uint32_t)((wn * 32 + (lane & 7) + ((lane & 8) ? 8 : 0)) * 256);

    float s_r[4]; int rowid[4];
    #pragma unroll
    for (int mi = 0; mi < 2; ++mi)
        #pragma unroll
        for (int h = 0; h < 2; ++h) {
            int rr = wm * 32 + mi * 16 + (lane >> 2) + 8 * h;
            rowid[mi * 2 + h] = rr;
            s_r[mi * 2 + h] = srow[rr];
        }
    // per-slot top-3: (v0,i0,v1,i1,v2)
    float tv0[4], tv1[4], tv2[4]; int ti0[4], ti1[4];
    #pragma unroll
    for (int s = 0; s < 4; ++s) {
        tv0[s] = CUDART_INF_F; tv1[s] = CUDART_INF_F; tv2[s] = CUDART_INF_F;
        ti0[s] = 0; ti1[s] = 0;
    }

    for (int c = 0; c < CHUNKS; ++c) {
        if (c < CHUNKS - 2) CP_WAIT2(); else if (c == CHUNKS - 2) CP_WAIT1(); else CP_WAIT0();
        __syncthreads();
        if (c + 3 < CHUNKS)
            fill_async(sb + OFF_B + ((c + 3) & 3) * BUFSZ, c + 3, tid);
        const uint32_t bBase = sb + OFF_B + (c & 3) * BUFSZ;

        float acc[2][4][4];
        #pragma unroll
        for (int i = 0; i < 32; ++i) ((float*)acc)[i] = 0.f;

        #pragma unroll
        for (int ks = 0; ks < 8; ++ks) {
            const int C = ks * 2 + klane;
            const uint32_t slot = (uint32_t)(((C & ~7) | ((C & 7) ^ rx7)) << 4);
            uint32_t A0[4], A1[4], B0[4], B1[4];
            ldsm4(A0, aRow0 + slot);
            ldsm4(A1, aRow0 + 16 * 256 + slot);
            ldsm4(B0, bBase + bRowOff + slot);
            ldsm4(B1, bBase + bRowOff + 16 * 256 + slot);
            mma16816(acc[0][0], A0, B0[0], B0[2]);
            mma16816(acc[0][1], A0, B0[1], B0[3]);
            mma16816(acc[0][2], A0, B1[0], B1[2]);
            mma16816(acc[0][3], A0, B1[1], B1[3]);
            mma16816(acc[1][0], A1, B0[0], B0[2]);
            mma16816(acc[1][1], A1, B0[1], B0[3]);
            mma16816(acc[1][2], A1, B1[0], B1[2]);
            mma16816(acc[1][3], A1, B1[1], B1[3]);
        }

        const int cb0 = c * CHUNK + wn * 32 + 2 * (lane & 3);
        #pragma unroll
        for (int mi = 0; mi < 2; ++mi)
            #pragma unroll
            for (int ni = 0; ni < 4; ++ni) {
                const float* cc = acc[mi][ni];
                int code = cb0 + ni * 8;
                float t0 = tall[code], t1 = tall[code + 1];
                #pragma unroll
                for (int h = 0; h < 2; ++h) {
                    int s = mi * 2 + h;
                    float d0 = __fadd_rn(__fsub_rn(s_r[s], __fmul_rn(cc[2 * h],     9.765625e-4f)), t0);
                    float d1 = __fadd_rn(__fsub_rn(s_r[s], __fmul_rn(cc[2 * h + 1], 9.765625e-4f)), t1);
                    // ascending codes per slot; ties keep earlier (lower index)
                    if (d0 < tv2[s]) {
                        if (d0 < tv0[s])      { tv2[s]=tv1[s]; tv1[s]=tv0[s]; ti1[s]=ti0[s]; tv0[s]=d0; ti0[s]=code; }
                        else if (d0 < tv1[s]) { tv2[s]=tv1[s]; tv1[s]=d0; ti1[s]=code; }
                        else                  { tv2[s]=d0; }
                    }
                    if (d1 < tv2[s]) {
                        if (d1 < tv0[s])      { tv2[s]=tv1[s]; tv1[s]=tv0[s]; ti1[s]=ti0[s]; tv0[s]=d1; ti0[s]=code+1; }
                        else if (d1 < tv1[s]) { tv2[s]=tv1[s]; tv1[s]=d1; ti1[s]=code+1; }
                        else                  { tv2[s]=d1; }
                    }
                }
            }
    }

    // quad reduce: merge top-3 lists (lexicographic for top-2; value-only 3rd)
    #pragma unroll
    for (int s = 0; s < 4; ++s) {
        float v0 = tv0[s], v1 = tv1[s], v2 = tv2[s];
        int i0 = ti0[s], i1 = ti1[s];
        #pragma unroll
        for (int off = 2; off > 0; off >>= 1) {
            float V0 = __shfl_down_sync(0xffffffffu, v0, off, 4);
            float V1 = __shfl_down_sync(0xffffffffu, v1, off, 4);
            float V2 = __shfl_down_sync(0xffffffffu, v2, off, 4);
            int   I0 = __shfl_down_sync(0xffffffffu, i0, off, 4);
            int   I1 = __shfl_down_sync(0xffffffffu, i1, off, 4);
            float nv2 = third3(v0, v1, v2, V0, V1, V2);
            bool bf = (V0 < v0) || (V0 == v0 && I0 < i0);
            float nv0 = bf ? V0 : v0; int ni0 = bf ? I0 : i0;
            float ca  = bf ? v0 : V0; int cia = bf ? i0 : I0;
            float cbv = bf ? V1 : v1; int cib = bf ? I1 : i1;
            bool sbv = (cbv < ca) || (cbv == ca && cib < cia);
            float nv1 = sbv ? cbv : ca; int ni1 = sbv ? cib : cia;
            v0 = nv0; i0 = ni0; v1 = nv1; i1 = ni1; v2 = nv2;
        }
        tv0[s] = v0; tv1[s] = v1; tv2[s] = v2; ti0[s] = i0; ti1[s] = i1;
    }
    if (wn == 0 && (lane & 3) == 0) {
        #pragma unroll
        for (int s = 0; s < 4; ++s) {
            int r = rowid[s];
            V0A[r] = tv0[s]; I0A[r] = ti0[s];
            V1A[r] = tv1[s]; I1A[r] = ti1[s];
            V2A[r] = tv2[s];
        }
    }
    __syncthreads();
    if (wn == 1 && (lane & 3) == 0) {
        #pragma unroll
        for (int s = 0; s < 4; ++s) {
            int r = rowid[s];
            float a0 = V0A[r], a1 = V1A[r], a2 = V2A[r];
            int ai0 = I0A[r], ai1 = I1A[r];
            float b0 = tv0[s], b1 = tv1[s], b2 = tv2[s];
            int bi0 = ti0[s], bi1 = ti1[s];
            float nv2 = third3(a0, a1, a2, b0, b1, b2);
            bool bf = (b0 < a0) || (b0 == a0 && bi0 < ai0);
            float nv0 = bf ? b0 : a0; int ni0 = bf ? bi0 : ai0;
            float ca  = bf ? a0 : b0; int cia = bf ? ai0 : bi0;
            float cbv = bf ? b1 : a1; int cib = bf ? bi1 : ai1;
            bool sbv = (cbv < ca) || (cbv == ca && cib < cia);
            float nv1 = sbv ? cbv : ca; int ni1 = sbv ? cib : cia;

            int row = rbase + r;
            // margin >= 2*(max|2m~-2m| + ulp(d)): 2e-5 abs + 5e-7*v0
            float margin = __fmaf_rn(nv0, 5e-7f, 2e-5f);
            if (nv1 - nv0 > margin) {
                g_idx[row] = ni0;
            } else if (nv2 - nv0 > margin) {
                int p = atomicAdd(&g_cntA, 1);
                g_listA[p] = make_int4(row, ni0, ni1, 0);
            } else {
                int p = atomicAdd(&g_cntB, 1);
                g_listB[p] = row;
            }
        }
    }
}

// ---- fix A: exact compare of 2 candidates, thread per row ----
__global__ __launch_bounds__(256)
void k_fixA(const float* __restrict__ z, const float* __restrict__ emb) {
    int idx = blockIdx.x * 256 + threadIdx.x;
    if (idx >= g_cntA) return;
    int4 ent = g_listA[idx];
    int row = ent.x, ia = ent.y, ib = ent.z;
    const float4* z4 = (const float4*)(z + (size_t)row * DIM);
    const float4* a4 = (const float4*)(emb + (size_t)ia * DIM);
    const float4* b4 = (const float4*)(emb + (size_t)ib * DIM);
    float s = 0.f, ma = 0.f, mb = 0.f;
    #pragma unroll 8
    for (int k4 = 0; k4 < 32; ++k4) {
        float4 zv = z4[k4], av = a4[k4], bv = b4[k4];
        s  = __fadd_rn(s, __fmul_rn(zv.x, zv.x));
        s  = __fadd_rn(s, __fmul_rn(zv.y, zv.y));
        s  = __fadd_rn(s, __fmul_rn(zv.z, zv.z));
        s  = __fadd_rn(s, __fmul_rn(zv.w, zv.w));
        ma = __fmaf_rn(zv.x, av.x, ma); ma = __fmaf_rn(zv.y, av.y, ma);
        ma = __fmaf_rn(zv.z, av.z, ma); ma = __fmaf_rn(zv.w, av.w, ma);
        mb = __fmaf_rn(zv.x, bv.x, mb); mb = __fmaf_rn(zv.y, bv.y, mb);
        mb = __fmaf_rn(zv.z, bv.z, mb); mb = __fmaf_rn(zv.w, bv.w, mb);
    }
    float da = __fadd_rn(__fsub_rn(s, __fmul_rn(2.f, ma)), g_t[ia]);
    float db = __fadd_rn(__fsub_rn(s, __fmul_rn(2.f, mb)), g_t[ib]);
    int win;
    if (db < da) win = ib;
    else if (da < db) win = ia;
    else win = min(ia, ib);
    g_idx[row] = win;
}

// ---- fix B: full exact scan, block per row ----
__global__ __launch_bounds__(256)
void k_fixB(const float* __restrict__ z, const float* __restrict__ emb) {
    __shared__ float zs[DIM];
    __shared__ float rv[256];
    __shared__ int   ri[256];
    const int tid = threadIdx.x;
    const int cnt = g_cntB;

    for (int bi = blockIdx.x; bi < cnt; bi += gridDim.x) {
        int row = g_listB[bi];
        __syncthreads();
        if (tid < 32)
            ((float4*)zs)[tid] = ((const float4*)(z + (size_t)row * DIM))[tid];
        __syncthreads();

        float s = 0.f;
        #pragma unroll 8
        for (int k = 0; k < DIM; ++k)
            s = __fadd_rn(s, __fmul_rn(zs[k], zs[k]));

        float best = CUDART_INF_F; int bix = 0;
        #pragma unroll
        for (int j = 0; j < 8; ++j) {
            int c = j * 256 + tid;
            const float4* e4 = (const float4*)(emb + (size_t)c * DIM);
            const float4* z4 = (const float4*)zs;
            float m = 0.f;
            #pragma unroll 8
            for (int k4 = 0; k4 < 32; ++k4) {
                float4 zv = z4[k4], ev = e4[k4];
                m = __fmaf_rn(zv.x, ev.x, m); m = __fmaf_rn(zv.y, ev.y, m);
                m = __fmaf_rn(zv.z, ev.z, m); m = __fmaf_rn(zv.w, ev.w, m);
            }
            float d = __fadd_rn(__fsub_rn(s, __fmul_rn(2.f, m)), g_t[c]);
            if (d < best) { best = d; bix = c; }
        }
        rv[tid] = best; ri[tid] = bix;
        __syncthreads();
        for (int w = 128; w > 0; w >>= 1) {
            if (tid < w) {
                float o = rv[tid + w]; int oi = ri[tid + w];
                if (o < rv[tid] || (o == rv[tid] && oi < ri[tid])) { rv[tid] = o; ri[tid] = oi; }
            }
            __syncthreads();
        }
        if (tid == 0) g_idx[row] = ri[0];
    }
}

// ---- gather + straight-through + indices + loss partials ----
__global__ __launch_bounds__(256)
void k_out(const float* __restrict__ z, const float* __restrict__ emb,
           float* __restrict__ out, long long out_size) {
    __shared__ float red[256];
    const int tid = threadIdx.x;
    const long long row0 = (long long)blockIdx.x * 64;
    float lsum = 0.f;

    for (int i = tid; i < 64 * (DIM / 4); i += 256) {
        long long r  = row0 + (i >> 5);
        int       d4 = (i & 31) * 4;
        int idx = g_idx[r];
        float4 q  = *(const float4*)(emb + (size_t)idx * DIM + d4);
        long long gi = r * DIM + d4;
        float4 zz = *(const float4*)(z + gi);
        float4 o; float df;
        df = __fsub_rn(q.x, zz.x); o.x = __fadd_rn(zz.x, df); lsum += df * df;
        df = __fsub_rn(q.y, zz.y); o.y = __fadd_rn(zz.y, df); lsum += df * df;
        df = __fsub_rn(q.z, zz.z); o.z = __fadd_rn(zz.z, df); lsum += df * df;
        df = __fsub_rn(q.w, zz.w); o.w = __fadd_rn(zz.w, df); lsum += df * df;
        if (gi + 3 < out_size) *(float4*)(out + gi) = o;
    }

    if (tid < 64) {
        long long r  = row0 + tid;
        long long gi = (long long)NZ + r;
        if (gi < out_size) out[gi] = (float)g_idx[r];
    }

    red[tid] = lsum;
    __syncthreads();
    for (int s = 128; s > 0; s >>= 1) {
        if (tid < s) red[tid] += red[tid + s];
        __syncthreads();
    }
    if (tid == 0) g_part[blockIdx.x] = red[0];
}

// ---- deterministic final loss reduce ----
__global__ void k_final(float* __restrict__ out, long long out_size) {
    __shared__ float red[256];
    const int tid = threadIdx.x;
    float s = 0.f;
    for (int i = tid; i < 1024; i += 256) s += g_part[i];
    red[tid] = s;
    __syncthreads();
    for (int w = 128; w > 0; w >>= 1) {
        if (tid < w) red[tid] += red[tid + w];
        __syncthreads();
    }
    if (tid == 0) {
        float m = red[0] / (float)NZ;
        float loss = __fadd_rn(m, __fmul_rn(0.25f, m));
        long long li = (long long)NZ + NROWS;
        if (li < out_size) out[li] = loss;
    }
}

extern "C" void kernel_launch(void* const* d_in, const int* in_sizes, int n_in,
                              void* d_out, int out_size) {
    const float* z   = (const float*)d_in[0];
    const float* emb = (const float*)d_in[1];
    float* out = (float*)d_out;

    cudaFuncSetAttribute(k_argmin_tc, cudaFuncAttributeMaxDynamicSharedMemorySize, SMEM_SZ);

    k_embnorm<<<16, 128>>>(emb);
    k_split<<<(KCODES * DIM) / 256, 256>>>(emb);
    k_argmin_tc<<<NROWS / TILE_M, NTH, SMEM_SZ>>>(z);
    k_fixA<<<NROWS / 256, 256>>>(z, emb);
    k_fixB<<<512, 256>>>(z, emb);
    k_out<<<NROWS / 64, 256>>>(z, emb, out, (long long)out_size);
    k_final<<<1, 256>>>(out, (long long)out_size);
}

// round 13
// speedup vs baseline: 1.4311x; 1.4311x over previous
#include <cuda_runtime.h>
#include <cuda_fp16.h>
#include <math_constants.h>
#include <cstdint>

#define DIM 128
#define KCODES 2048
#define NROWS 65536
#define NZ (NROWS * DIM)
#define TILE_M 128
#define CHUNK 64
#define CHUNKS 32
#define NTH 256

__device__ __align__(16) float g_t[KCODES];
__device__ int   g_idx[NROWS];
__device__ float g_part[1024];
__device__ __align__(16) __half g_bh[KCODES * DIM];   // fl16(2048*e)
__device__ int g_cnt;
__device__ int g_list[NROWS];

// ---- smem byte offsets (stage 1): ~106 KB -> 2 CTAs/SM ----
#define OFF_A    0
#define OFF_B    32768
#define BUFSZ    16384
#define OFF_TALL 98304
#define OFF_SROW 106496
#define OFF_BEST 107008
#define OFF_IDX  107520
#define OFF_B2   108032
#define SMEM_SZ  108544

// ---- PTX helpers ----
static __device__ __forceinline__ void ldsm4(uint32_t* r, uint32_t a) {
    asm volatile("ldmatrix.sync.aligned.m8n8.x4.shared.b16 {%0,%1,%2,%3}, [%4];"
                 : "=r"(r[0]), "=r"(r[1]), "=r"(r[2]), "=r"(r[3]) : "r"(a));
}
static __device__ __forceinline__ void mma16816(float* c, const uint32_t* a,
                                                uint32_t b0, uint32_t b1) {
    asm volatile("mma.sync.aligned.m16n8k16.row.col.f32.f16.f16.f32 "
                 "{%0,%1,%2,%3}, {%4,%5,%6,%7}, {%8,%9}, {%0,%1,%2,%3};"
                 : "+f"(c[0]), "+f"(c[1]), "+f"(c[2]), "+f"(c[3])
                 : "r"(a[0]), "r"(a[1]), "r"(a[2]), "r"(a[3]), "r"(b0), "r"(b1));
}
#define CP_ASYNC16(d, s) asm volatile("cp.async.ca.shared.global [%0], [%1], 16;" :: "r"(d), "l"(s))
#define CP_COMMIT() asm volatile("cp.async.commit_group;" ::: "memory")
#define CP_WAIT0()  asm volatile("cp.async.wait_group 0;" ::: "memory")
#define CP_WAIT1()  asm volatile("cp.async.wait_group 1;" ::: "memory")
#define CP_WAIT2()  asm volatile("cp.async.wait_group 2;" ::: "memory")

// ---- f32x2 helpers for exact-GEMM fixup ----
#define FMA2(d, a, b) asm("fma.rn.f32x2 %0, %1, %2, %0;" : "+l"(d) : "l"(a), "l"(b))
static __device__ __forceinline__ unsigned long long pack2(float x) {
    unsigned long long r;
    unsigned int u = __float_as_uint(x);
    asm("mov.b64 %0, {%1, %1};" : "=l"(r) : "r"(u));
    return r;
}
static __device__ __forceinline__ void unpack2(unsigned long long v, float& lo, float& hi) {
    unsigned int a, b;
    asm("mov.b64 {%0, %1}, %2;" : "=r"(a), "=r"(b) : "l"(v));
    lo = __uint_as_float(a);
    hi = __uint_as_float(b);
}

// ---- prep: ||e||^2, exact sequential fp32, coalesced; zero counter ----
__global__ __launch_bounds__(128)
void k_embnorm(const float* __restrict__ emb) {
    __shared__ float sm[128 * 33];
    const int tid = threadIdx.x;
    const int cb = blockIdx.x * 128;
    if (blockIdx.x == 0 && tid == 0) g_cnt = 0;
    float s = 0.f;
    for (int kc = 0; kc < 4; ++kc) {
        __syncthreads();
        for (int i = tid; i < 128 * 32; i += 128) {
            int cl = i >> 5, kk = i & 31;
            sm[cl * 33 + kk] = emb[(size_t)(cb + cl) * DIM + kc * 32 + kk];
        }
        __syncthreads();
        #pragma unroll 8
        for (int kk = 0; kk < 32; ++kk) {
            float v = sm[tid * 33 + kk];
            s = __fadd_rn(s, __fmul_rn(v, v));
        }
    }
    g_t[cb + tid] = s;
}

// ---- prep: f16 codebook scaled by 2048 (exact power of 2) ----
__global__ void k_split(const float* __restrict__ emb) {
    int idx = blockIdx.x * blockDim.x + threadIdx.x;
    g_bh[idx] = __float2half_rn(__fmul_rn(emb[idx], 2048.0f));
}

// ---- B-chunk async fill ----
static __device__ __forceinline__ void fill_async(uint32_t bBase, int chunk, int tid) {
    const char* src = (const char*)g_bh + (size_t)chunk * CHUNK * 256;
    #pragma unroll
    for (int j = 0; j < 4; ++j) {
        int i = tid + j * NTH;
        int code = i >> 4;
        int kg = i & 15;
        uint32_t d = bBase + (uint32_t)(code * 256 + (((kg & ~7) | ((kg ^ code) & 7)) << 4));
        CP_ASYNC16(d, src + code * 256 + kg * 16);
    }
    CP_COMMIT();
}

// ---- stage 1: pure-f16 HMMA GEMM (K=128) + argmin + top-2 margin flag (R11 verbatim) ----
__global__ __launch_bounds__(NTH, 2)
void k_argmin_tc(const float* __restrict__ z) {
    extern __shared__ char smc[];
    uint32_t sb;
    asm("{ .reg .u64 t; cvta.to.shared.u64 t, %1; cvt.u32.u64 %0, t; }" : "=r"(sb) : "l"(smc));
    float* tall  = (float*)(smc + OFF_TALL);
    float* srow  = (float*)(smc + OFF_SROW);
    float* bestA = (float*)(smc + OFF_BEST);
    int*   idxA  = (int*)(smc + OFF_IDX);
    float* b2A   = (float*)(smc + OFF_B2);

    const int tid = threadIdx.x;
    const int lane = tid & 31, wid = tid >> 5;
    const int wm = wid & 3, wn = wid >> 2;
    const int rbase = blockIdx.x * TILE_M;

    fill_async(sb + OFF_B + 0 * BUFSZ, 0, tid);
    fill_async(sb + OFF_B + 1 * BUFSZ, 1, tid);
    fill_async(sb + OFF_B + 2 * BUFSZ, 2, tid);

    for (int i = tid; i < KCODES / 4; i += NTH)
        ((float4*)tall)[i] = ((const float4*)g_t)[i];

    {
        int r = tid >> 1, half = tid & 1;
        const float* zr = z + (size_t)(rbase + r) * DIM + half * 64;
        char* arow = smc + OFF_A + r * 256;
        int rx = r & 7;
        #pragma unroll
        for (int g = 0; g < 8; ++g) {
            float4 v0 = *(const float4*)(zr + g * 8);
            float4 v1 = *(const float4*)(zr + g * 8 + 4);
            float f[8] = {v0.x, v0.y, v0.z, v0.w, v1.x, v1.y, v1.z, v1.w};
            uint32_t hp[4];
            #pragma unroll
            for (int e = 0; e < 4; ++e) {
                __half a = __float2half_rn(f[2 * e]);
                __half b = __float2half_rn(f[2 * e + 1]);
                hp[e] = (uint32_t)__half_as_ushort(a) | ((uint32_t)__half_as_ushort(b) << 16);
            }
            int kg0 = half * 8 + g;
            int ks0 = (kg0 & ~7) | ((kg0 & 7) ^ rx);
            *(uint4*)(arow + ks0 * 16) = *(uint4*)hp;
        }
    }

    if (tid < TILE_M) {
        const float* zr = z + (size_t)(rbase + tid) * DIM;
        float s = 0.f;
        #pragma unroll 8
        for (int k = 0; k < DIM; ++k)
            s = __fadd_rn(s, __fmul_rn(zr[k], zr[k]));
        srow[tid] = s;
    }
    __syncthreads();

    const int rx7 = lane & 7;
    const int klane = (lane >> 4) & 1;
    const uint32_t aRow0 = sb + OFF_A +
        (uint32_t)((wm * 32 + (lane & 7) + ((lane & 8) ? 8 : 0)) * 256);
    const uint32_t bRowOff =
        (uint32_t)((wn * 32 + (lane & 7) + ((lane & 8) ? 8 : 0)) * 256);

    float s_r[4]; int rowid[4];
    #pragma unroll
    for (int mi = 0; mi < 2; ++mi)
        #pragma unroll
        for (int h = 0; h < 2; ++h) {
            int rr = wm * 32 + mi * 16 + (lane >> 2) + 8 * h;
            rowid[mi * 2 + h] = rr;
            s_r[mi * 2 + h] = srow[rr];
        }
    float best[4], bsec[4]; int bidx[4];
    #pragma unroll
    for (int s = 0; s < 4; ++s) { best[s] = CUDART_INF_F; bsec[s] = CUDART_INF_F; bidx[s] = 0; }

    for (int c = 0; c < CHUNKS; ++c) {
        if (c < CHUNKS - 2) CP_WAIT2(); else if (c == CHUNKS - 2) CP_WAIT1(); else CP_WAIT0();
        __syncthreads();
        if (c + 3 < CHUNKS)
            fill_async(sb + OFF_B + ((c + 3) & 3) * BUFSZ, c + 3, tid);
        const uint32_t bBase = sb + OFF_B + (c & 3) * BUFSZ;

        float acc[2][4][4];
        #pragma unroll
        for (int i = 0; i < 32; ++i) ((float*)acc)[i] = 0.f;

        #pragma unroll
        for (int ks = 0; ks < 8; ++ks) {
            const int C = ks * 2 + klane;
            const uint32_t slot = (uint32_t)(((C & ~7) | ((C & 7) ^ rx7)) << 4);
            uint32_t A0[4], A1[4], B0[4], B1[4];
            ldsm4(A0, aRow0 + slot);
            ldsm4(A1, aRow0 + 16 * 256 + slot);
            ldsm4(B0, bBase + bRowOff + slot);
            ldsm4(B1, bBase + bRowOff + 16 * 256 + slot);
            mma16816(acc[0][0], A0, B0[0], B0[2]);
            mma16816(acc[0][1], A0, B0[1], B0[3]);
            mma16816(acc[0][2], A0, B1[0], B1[2]);
            mma16816(acc[0][3], A0, B1[1], B1[3]);
            mma16816(acc[1][0], A1, B0[0], B0[2]);
            mma16816(acc[1][1], A1, B0[1], B0[3]);
            mma16816(acc[1][2], A1, B1[0], B1[2]);
            mma16816(acc[1][3], A1, B1[1], B1[3]);
        }

        const int cb0 = c * CHUNK + wn * 32 + 2 * (lane & 3);
        #pragma unroll
        for (int mi = 0; mi < 2; ++mi)
            #pragma unroll
            for (int ni = 0; ni < 4; ++ni) {
                const float* cc = acc[mi][ni];
                int code = cb0 + ni * 8;
                float t0 = tall[code], t1 = tall[code + 1];
                #pragma unroll
                for (int h = 0; h < 2; ++h) {
                    int s = mi * 2 + h;
                    float d0 = __fadd_rn(__fsub_rn(s_r[s], __fmul_rn(cc[2 * h],     9.765625e-4f)), t0);
                    float d1 = __fadd_rn(__fsub_rn(s_r[s], __fmul_rn(cc[2 * h + 1], 9.765625e-4f)), t1);
                    if (d0 < best[s]) { bsec[s] = best[s]; best[s] = d0; bidx[s] = code; }
                    else if (d0 < bsec[s]) bsec[s] = d0;
                    if (d1 < best[s]) { bsec[s] = best[s]; best[s] = d1; bidx[s] = code + 1; }
                    else if (d1 < bsec[s]) bsec[s] = d1;
                }
            }
    }

    #pragma unroll
    for (int s = 0; s < 4; ++s) {
        float v = best[s], v2 = bsec[s]; int ix = bidx[s];
        #pragma unroll
        for (int off = 2; off > 0; off >>= 1) {
            float o1 = __shfl_down_sync(0xffffffffu, v, off, 4);
            int   oi = __shfl_down_sync(0xffffffffu, ix, off, 4);
            float o2 = __shfl_down_sync(0xffffffffu, v2, off, 4);
            if (o1 < v || (o1 == v && oi < ix)) { v2 = fminf(v, o2); v = o1; ix = oi; }
            else { v2 = fminf(v2, o1); }
        }
        best[s] = v; bsec[s] = v2; bidx[s] = ix;
    }
    if (wn == 0 && (lane & 3) == 0) {
        #pragma unroll
        for (int s = 0; s < 4; ++s) {
            bestA[rowid[s]] = best[s]; idxA[rowid[s]] = bidx[s]; b2A[rowid[s]] = bsec[s];
        }
    }
    __syncthreads();
    if (wn == 1 && (lane & 3) == 0) {
        #pragma unroll
        for (int s = 0; s < 4; ++s) {
            float a1 = bestA[rowid[s]], a2 = b2A[rowid[s]]; int ai = idxA[rowid[s]];
            float c1 = best[s], c2 = bsec[s]; int ci = bidx[s];
            float nb1, nb2; int ni1;
            if (c1 < a1 || (c1 == a1 && ci < ai)) { nb1 = c1; ni1 = ci; nb2 = fminf(a1, c2); }
            else { nb1 = a1; ni1 = ai; nb2 = fminf(a2, c1); }
            int row = rbase + rowid[s];
            g_idx[row] = ni1;
            float margin = __fmaf_rn(nb1, 3e-7f, 3e-5f);
            if (!(nb2 - nb1 > margin)) {
                int pos = atomicAdd(&g_cnt, 1);
                g_list[pos] = row;
            }
        }
    }
}

// ---- stage 2: exact f32x2-FFMA full-scan GEMM over gathered flagged rows ----
// 64-row gathered tiles, 128 threads, thread tile 8 rows x 8 codes, 2 CTAs/SM.
// Identical sequential-k fp32 chain as the proven R1-R4 kernels.
#define XTM 64
#define XTN 128
__global__ __launch_bounds__(128, 2)
void k_exact_gemm(const float* __restrict__ z, const float* __restrict__ emb) {
    extern __shared__ char smx[];
    float* zs   = (float*)smx;                    // [128k][64r]      32 KB
    float* es   = zs + DIM * XTM;                 // [128k][128c] swz 64 KB
    float* tall = es + DIM * XTN;                 // [2048]            8 KB
    float* ss   = tall + KCODES;                  // [64]

    const int tid = threadIdx.x;
    const int cnt = g_cnt;

    for (int i = tid; i < KCODES / 4; i += 128)
        ((float4*)tall)[i] = ((const float4*)g_t)[i];

    const int tc = tid & 15;   // codes {4tc..4tc+3} U {64+4tc..+3} per chunk
    const int tr = tid >> 4;   // rows 8tr..8tr+7

    for (int base = blockIdx.x * XTM; base < cnt; base += gridDim.x * XTM) {
        __syncthreads();   // previous tile fully done (zs/es reuse)

        // gather z rows (clamped duplicates in the tail), transpose k-major
        for (int i = tid; i < XTM * (DIM / 4); i += 128) {
            int r  = i & (XTM - 1);
            int k4 = i >> 6;
            int row = g_list[min(base + r, cnt - 1)];
            float4 v = *(const float4*)(z + (size_t)row * DIM + k4 * 4);
            zs[(k4 * 4 + 0) * XTM + r] = v.x;
            zs[(k4 * 4 + 1) * XTM + r] = v.y;
            zs[(k4 * 4 + 2) * XTM + r] = v.z;
            zs[(k4 * 4 + 3) * XTM + r] = v.w;
        }
        __syncthreads();

        if (tid < XTM) {
            float s = 0.f;
            #pragma unroll 8
            for (int k = 0; k < DIM; ++k) {
                float v = zs[k * XTM + tid];
                s = __fadd_rn(s, __fmul_rn(v, v));
            }
            ss[tid] = s;
        }
        __syncthreads();

        float s_r[8];
        #pragma unroll
        for (int r = 0; r < 8; ++r) s_r[r] = ss[tr * 8 + r];

        float best[8]; int bidx[8];
        #pragma unroll
        for (int r = 0; r < 8; ++r) { best[r] = CUDART_INF_F; bidx[r] = 0; }

        for (int ch = 0; ch < KCODES / XTN; ++ch) {
            const int cbase = ch * XTN;
            __syncthreads();
            // e chunk: coalesced read, group-swizzled STS
            #pragma unroll 4
            for (int it = 0; it < XTN / 4; ++it) {
                int cl = it * 4 + (tid >> 5);
                int k4 = tid & 31;
                float4 v = *(const float4*)(emb + (size_t)(cbase + cl) * DIM + k4 * 4);
                int g = cl >> 2, off = cl & 3;
                #pragma unroll
                for (int j = 0; j < 4; ++j) {
                    int k = k4 * 4 + j;
                    es[k * XTN + (((g ^ (k >> 2)) << 2) | off)] = ((const float*)&v)[j];
                }
            }
            __syncthreads();

            unsigned long long acc[32];
            #pragma unroll
            for (int i = 0; i < 32; ++i) acc[i] = 0ull;

            #pragma unroll 4
            for (int k = 0; k < DIM; ++k) {
                const float* ek = es + k * XTN;
                const int sw = k >> 2;
                ulonglong2 eA = *(const ulonglong2*)(ek + ((tc ^ sw) << 2));
                ulonglong2 eB = *(const ulonglong2*)(ek + (((tc + 16) ^ sw) << 2));
                const float* zk = zs + k * XTM + tr * 8;
                float4 za = *(const float4*)(zk);
                float4 zb = *(const float4*)(zk + 4);
                unsigned long long zp[8];
                zp[0] = pack2(za.x); zp[1] = pack2(za.y);
                zp[2] = pack2(za.z); zp[3] = pack2(za.w);
                zp[4] = pack2(zb.x); zp[5] = pack2(zb.y);
                zp[6] = pack2(zb.z); zp[7] = pack2(zb.w);
                #pragma unroll
                for (int r = 0; r < 8; ++r) {
                    FMA2(acc[r * 4 + 0], zp[r], eA.x);
                    FMA2(acc[r * 4 + 1], zp[r], eA.y);
                    FMA2(acc[r * 4 + 2], zp[r], eB.x);
                    FMA2(acc[r * 4 + 3], zp[r], eB.y);
                }
            }

            // dist = fl(fl(s - 2m) + t); ascending codes; strict <
            #pragma unroll
            for (int r = 0; r < 8; ++r) {
                #pragma unroll
                for (int p = 0; p < 4; ++p) {
                    float mlo, mhi;
                    unpack2(acc[r * 4 + p], mlo, mhi);
                    int clocal = (p < 2) ? (tc * 4 + p * 2) : (64 + tc * 4 + (p - 2) * 2);
                    int c0 = cbase + clocal;
                    float d0 = __fadd_rn(__fsub_rn(s_r[r], __fmul_rn(2.f, mlo)), tall[c0]);
                    float d1 = __fadd_rn(__fsub_rn(s_r[r], __fmul_rn(2.f, mhi)), tall[c0 + 1]);
                    if (d0 < best[r]) { best[r] = d0; bidx[r] = c0; }
                    if (d1 < best[r]) { best[r] = d1; bidx[r] = c0 + 1; }
                }
            }
        }

        // 16-lane (tc group) reduce, tie -> lowest index; write valid rows
        #pragma unroll
        for (int r = 0; r < 8; ++r) {
            float v = best[r]; int ix = bidx[r];
            #pragma unroll
            for (int off = 8; off > 0; off >>= 1) {
                float v2 = __shfl_down_sync(0xffffffffu, v, off, 16);
                int   i2 = __shfl_down_sync(0xffffffffu, ix, off, 16);
                if (v2 < v || (v2 == v && i2 < ix)) { v = v2; ix = i2; }
            }
            int rl = tr * 8 + r;
            if (tc == 0 && base + rl < cnt)
                g_idx[g_list[base + rl]] = ix;
        }
    }
}

// ---- gather + straight-through + indices + loss partials ----
__global__ __launch_bounds__(256)
void k_out(const float* __restrict__ z, const float* __restrict__ emb,
           float* __restrict__ out, long long out_size) {
    __shared__ float red[256];
    const int tid = threadIdx.x;
    const long long row0 = (long long)blockIdx.x * 64;
    float lsum = 0.f;

    for (int i = tid; i < 64 * (DIM / 4); i += 256) {
        long long r  = row0 + (i >> 5);
        int       d4 = (i & 31) * 4;
        int idx = g_idx[r];
        float4 q  = *(const float4*)(emb + (size_t)idx * DIM + d4);
        long long gi = r * DIM + d4;
        float4 zz = *(const float4*)(z + gi);
        float4 o; float df;
        df = __fsub_rn(q.x, zz.x); o.x = __fadd_rn(zz.x, df); lsum += df * df;
        df = __fsub_rn(q.y, zz.y); o.y = __fadd_rn(zz.y, df); lsum += df * df;
        df = __fsub_rn(q.z, zz.z); o.z = __fadd_rn(zz.z, df); lsum += df * df;
        df = __fsub_rn(q.w, zz.w); o.w = __fadd_rn(zz.w, df); lsum += df * df;
        if (gi + 3 < out_size) *(float4*)(out + gi) = o;
    }

    if (tid < 64) {
        long long r  = row0 + tid;
        long long gi = (long long)NZ + r;
        if (gi < out_size) out[gi] = (float)g_idx[r];
    }

    red[tid] = lsum;
    __syncthreads();
    for (int s = 128; s > 0; s >>= 1) {
        if (tid < s) red[tid] += red[tid + s];
        __syncthreads();
    }
    if (tid == 0) g_part[blockIdx.x] = red[0];
}

// ---- deterministic final loss reduce ----
__global__ void k_final(float* __restrict__ out, long long out_size) {
    __shared__ float red[256];
    const int tid = threadIdx.x;
    float s = 0.f;
    for (int i = tid; i < 1024; i += 256) s += g_part[i];
    red[tid] = s;
    __syncthreads();
    for (int w = 128; w > 0; w >>= 1) {
        if (tid < w) red[tid] += red[tid + w];
        __syncthreads();
    }
    if (tid == 0) {
        float m = red[0] / (float)NZ;
        float loss = __fadd_rn(m, __fmul_rn(0.25f, m));
        long long li = (long long)NZ + NROWS;
        if (li < out_size) out[li] = loss;
    }
}

extern "C" void kernel_launch(void* const* d_in, const int* in_sizes, int n_in,
                              void* d_out, int out_size) {
    const float* z   = (const float*)d_in[0];
    const float* emb = (const float*)d_in[1];
    float* out = (float*)d_out;

    const int smem_x = DIM * XTM * 4 + DIM * XTN * 4 + KCODES * 4 + XTM * 4;
    cudaFuncSetAttribute(k_argmin_tc, cudaFuncAttributeMaxDynamicSharedMemorySize, SMEM_SZ);
    cudaFuncSetAttribute(k_exact_gemm, cudaFuncAttributeMaxDynamicSharedMemorySize, smem_x);

    k_embnorm<<<16, 128>>>(emb);
    k_split<<<(KCODES * DIM) / 256, 256>>>(emb);
    k_argmin_tc<<<NROWS / TILE_M, NTH, SMEM_SZ>>>(z);
    k_exact_gemm<<<256, 128, smem_x>>>(z, emb);
    k_out<<<NROWS / 64, 256>>>(z, emb, out, (long long)out_size);
    k_final<<<1, 256>>>(out, (long long)out_size);
}

// round 14
// speedup vs baseline: 1.4581x; 1.0188x over previous
#include <cuda_runtime.h>
#include <cuda_fp16.h>
#include <math_constants.h>
#include <cstdint>

#define DIM 128
#define KCODES 2048
#define NROWS 65536
#define NZ (NROWS * DIM)
#define TILE_M 128
#define CHUNK 64
#define CHUNKS 32
#define NTH 256

__device__ __align__(16) float g_t[KCODES];
__device__ int   g_idx[NROWS];
__device__ float g_part[1024];
__device__ __align__(16) __half g_bh[KCODES * DIM];   // fl16(2048*e)
__device__ int g_cnt;
__device__ int g_list[NROWS];

// ---- smem byte offsets (stage 1): ~106 KB -> 2 CTAs/SM ----
#define OFF_A    0
#define OFF_B    32768
#define BUFSZ    16384
#define OFF_TALL 98304
#define OFF_SROW 106496
#define OFF_BEST 107008
#define OFF_IDX  107520
#define OFF_B2   108032
#define SMEM_SZ  108544

// ---- PTX helpers ----
static __device__ __forceinline__ void ldsm4(uint32_t* r, uint32_t a) {
    asm volatile("ldmatrix.sync.aligned.m8n8.x4.shared.b16 {%0,%1,%2,%3}, [%4];"
                 : "=r"(r[0]), "=r"(r[1]), "=r"(r[2]), "=r"(r[3]) : "r"(a));
}
static __device__ __forceinline__ void mma16816(float* c, const uint32_t* a,
                                                uint32_t b0, uint32_t b1) {
    asm volatile("mma.sync.aligned.m16n8k16.row.col.f32.f16.f16.f32 "
                 "{%0,%1,%2,%3}, {%4,%5,%6,%7}, {%8,%9}, {%0,%1,%2,%3};"
                 : "+f"(c[0]), "+f"(c[1]), "+f"(c[2]), "+f"(c[3])
                 : "r"(a[0]), "r"(a[1]), "r"(a[2]), "r"(a[3]), "r"(b0), "r"(b1));
}
#define CP_ASYNC16(d, s) asm volatile("cp.async.ca.shared.global [%0], [%1], 16;" :: "r"(d), "l"(s))
#define CP_COMMIT() asm volatile("cp.async.commit_group;" ::: "memory")
#define CP_WAIT0()  asm volatile("cp.async.wait_group 0;" ::: "memory")
#define CP_WAIT1()  asm volatile("cp.async.wait_group 1;" ::: "memory")
#define CP_WAIT2()  asm volatile("cp.async.wait_group 2;" ::: "memory")

// ---- f32x2 helpers for exact-GEMM fixup ----
#define FMA2(d, a, b) asm("fma.rn.f32x2 %0, %1, %2, %0;" : "+l"(d) : "l"(a), "l"(b))
static __device__ __forceinline__ unsigned long long pack2(float x) {
    unsigned long long r;
    unsigned int u = __float_as_uint(x);
    asm("mov.b64 %0, {%1, %1};" : "=l"(r) : "r"(u));
    return r;
}
static __device__ __forceinline__ void unpack2(unsigned long long v, float& lo, float& hi) {
    unsigned int a, b;
    asm("mov.b64 {%0, %1}, %2;" : "=r"(a), "=r"(b) : "l"(v));
    lo = __uint_as_float(a);
    hi = __uint_as_float(b);
}

// ---- prep: ||e||^2, exact sequential fp32, coalesced; zero counter ----
__global__ __launch_bounds__(128)
void k_embnorm(const float* __restrict__ emb) {
    __shared__ float sm[128 * 33];
    const int tid = threadIdx.x;
    const int cb = blockIdx.x * 128;
    if (blockIdx.x == 0 && tid == 0) g_cnt = 0;
    float s = 0.f;
    for (int kc = 0; kc < 4; ++kc) {
        __syncthreads();
        for (int i = tid; i < 128 * 32; i += 128) {
            int cl = i >> 5, kk = i & 31;
            sm[cl * 33 + kk] = emb[(size_t)(cb + cl) * DIM + kc * 32 + kk];
        }
        __syncthreads();
        #pragma unroll 8
        for (int kk = 0; kk < 32; ++kk) {
            float v = sm[tid * 33 + kk];
            s = __fadd_rn(s, __fmul_rn(v, v));
        }
    }
    g_t[cb + tid] = s;
}

// ---- prep: f16 codebook scaled by 2048 (exact power of 2) ----
__global__ void k_split(const float* __restrict__ emb) {
    int idx = blockIdx.x * blockDim.x + threadIdx.x;
    g_bh[idx] = __float2half_rn(__fmul_rn(emb[idx], 2048.0f));
}

// ---- B-chunk async fill ----
static __device__ __forceinline__ void fill_async(uint32_t bBase, int chunk, int tid) {
    const char* src = (const char*)g_bh + (size_t)chunk * CHUNK * 256;
    #pragma unroll
    for (int j = 0; j < 4; ++j) {
        int i = tid + j * NTH;
        int code = i >> 4;
        int kg = i & 15;
        uint32_t d = bBase + (uint32_t)(code * 256 + (((kg & ~7) | ((kg ^ code) & 7)) << 4));
        CP_ASYNC16(d, src + code * 256 + kg * 16);
    }
    CP_COMMIT();
}

// ---- stage 1: pure-f16 HMMA GEMM (K=128) + argmin + top-2 margin flag ----
__global__ __launch_bounds__(NTH, 2)
void k_argmin_tc(const float* __restrict__ z) {
    extern __shared__ char smc[];
    uint32_t sb;
    asm("{ .reg .u64 t; cvta.to.shared.u64 t, %1; cvt.u32.u64 %0, t; }" : "=r"(sb) : "l"(smc));
    float* tall  = (float*)(smc + OFF_TALL);
    float* srow  = (float*)(smc + OFF_SROW);
    float* bestA = (float*)(smc + OFF_BEST);
    int*   idxA  = (int*)(smc + OFF_IDX);
    float* b2A   = (float*)(smc + OFF_B2);

    const int tid = threadIdx.x;
    const int lane = tid & 31, wid = tid >> 5;
    const int wm = wid & 3, wn = wid >> 2;
    const int rbase = blockIdx.x * TILE_M;

    fill_async(sb + OFF_B + 0 * BUFSZ, 0, tid);
    fill_async(sb + OFF_B + 1 * BUFSZ, 1, tid);
    fill_async(sb + OFF_B + 2 * BUFSZ, 2, tid);

    for (int i = tid; i < KCODES / 4; i += NTH)
        ((float4*)tall)[i] = ((const float4*)g_t)[i];

    {
        int r = tid >> 1, half = tid & 1;
        const float* zr = z + (size_t)(rbase + r) * DIM + half * 64;
        char* arow = smc + OFF_A + r * 256;
        int rx = r & 7;
        #pragma unroll
        for (int g = 0; g < 8; ++g) {
            float4 v0 = *(const float4*)(zr + g * 8);
            float4 v1 = *(const float4*)(zr + g * 8 + 4);
            float f[8] = {v0.x, v0.y, v0.z, v0.w, v1.x, v1.y, v1.z, v1.w};
            uint32_t hp[4];
            #pragma unroll
            for (int e = 0; e < 4; ++e) {
                __half a = __float2half_rn(f[2 * e]);
                __half b = __float2half_rn(f[2 * e + 1]);
                hp[e] = (uint32_t)__half_as_ushort(a) | ((uint32_t)__half_as_ushort(b) << 16);
            }
            int kg0 = half * 8 + g;
            int ks0 = (kg0 & ~7) | ((kg0 & 7) ^ rx);
            *(uint4*)(arow + ks0 * 16) = *(uint4*)hp;
        }
    }

    if (tid < TILE_M) {
        const float* zr = z + (size_t)(rbase + tid) * DIM;
        float s = 0.f;
        #pragma unroll 8
        for (int k = 0; k < DIM; ++k)
            s = __fadd_rn(s, __fmul_rn(zr[k], zr[k]));
        srow[tid] = s;
    }
    __syncthreads();

    const int rx7 = lane & 7;
    const int klane = (lane >> 4) & 1;
    const uint32_t aRow0 = sb + OFF_A +
        (uint32_t)((wm * 32 + (lane & 7) + ((lane & 8) ? 8 : 0)) * 256);
    const uint32_t bRowOff =
        (uint32_t)((wn * 32 + (lane & 7) + ((lane & 8) ? 8 : 0)) * 256);

    float s_r[4]; int rowid[4];
    #pragma unroll
    for (int mi = 0; mi < 2; ++mi)
        #pragma unroll
        for (int h = 0; h < 2; ++h) {
            int rr = wm * 32 + mi * 16 + (lane >> 2) + 8 * h;
            rowid[mi * 2 + h] = rr;
            s_r[mi * 2 + h] = srow[rr];
        }
    float best[4], bsec[4]; int bidx[4];
    #pragma unroll
    for (int s = 0; s < 4; ++s) { best[s] = CUDART_INF_F; bsec[s] = CUDART_INF_F; bidx[s] = 0; }

    for (int c = 0; c < CHUNKS; ++c) {
        if (c < CHUNKS - 2) CP_WAIT2(); else if (c == CHUNKS - 2) CP_WAIT1(); else CP_WAIT0();
        __syncthreads();
        if (c + 3 < CHUNKS)
            fill_async(sb + OFF_B + ((c + 3) & 3) * BUFSZ, c + 3, tid);
        const uint32_t bBase = sb + OFF_B + (c & 3) * BUFSZ;

        float acc[2][4][4];
        #pragma unroll
        for (int i = 0; i < 32; ++i) ((float*)acc)[i] = 0.f;

        #pragma unroll
        for (int ks = 0; ks < 8; ++ks) {
            const int C = ks * 2 + klane;
            const uint32_t slot = (uint32_t)(((C & ~7) | ((C & 7) ^ rx7)) << 4);
            uint32_t A0[4], A1[4], B0[4], B1[4];
            ldsm4(A0, aRow0 + slot);
            ldsm4(A1, aRow0 + 16 * 256 + slot);
            ldsm4(B0, bBase + bRowOff + slot);
            ldsm4(B1, bBase + bRowOff + 16 * 256 + slot);
            mma16816(acc[0][0], A0, B0[0], B0[2]);
            mma16816(acc[0][1], A0, B0[1], B0[3]);
            mma16816(acc[0][2], A0, B1[0], B1[2]);
            mma16816(acc[0][3], A0, B1[1], B1[3]);
            mma16816(acc[1][0], A1, B0[0], B0[2]);
            mma16816(acc[1][1], A1, B0[1], B0[3]);
            mma16816(acc[1][2], A1, B1[0], B1[2]);
            mma16816(acc[1][3], A1, B1[1], B1[3]);
        }

        const int cb0 = c * CHUNK + wn * 32 + 2 * (lane & 3);
        #pragma unroll
        for (int mi = 0; mi < 2; ++mi)
            #pragma unroll
            for (int ni = 0; ni < 4; ++ni) {
                const float* cc = acc[mi][ni];
                int code = cb0 + ni * 8;
                float t0 = tall[code], t1 = tall[code + 1];
                #pragma unroll
                for (int h = 0; h < 2; ++h) {
                    int s = mi * 2 + h;
                    float d0 = __fadd_rn(__fsub_rn(s_r[s], __fmul_rn(cc[2 * h],     9.765625e-4f)), t0);
                    float d1 = __fadd_rn(__fsub_rn(s_r[s], __fmul_rn(cc[2 * h + 1], 9.765625e-4f)), t1);
                    if (d0 < best[s]) { bsec[s] = best[s]; best[s] = d0; bidx[s] = code; }
                    else if (d0 < bsec[s]) bsec[s] = d0;
                    if (d1 < best[s]) { bsec[s] = best[s]; best[s] = d1; bidx[s] = code + 1; }
                    else if (d1 < bsec[s]) bsec[s] = d1;
                }
            }
    }

    #pragma unroll
    for (int s = 0; s < 4; ++s) {
        float v = best[s], v2 = bsec[s]; int ix = bidx[s];
        #pragma unroll
        for (int off = 2; off > 0; off >>= 1) {
            float o1 = __shfl_down_sync(0xffffffffu, v, off, 4);
            int   oi = __shfl_down_sync(0xffffffffu, ix, off, 4);
            float o2 = __shfl_down_sync(0xffffffffu, v2, off, 4);
            if (o1 < v || (o1 == v && oi < ix)) { v2 = fminf(v, o2); v = o1; ix = oi; }
            else { v2 = fminf(v2, o1); }
        }
        best[s] = v; bsec[s] = v2; bidx[s] = ix;
    }
    if (wn == 0 && (lane & 3) == 0) {
        #pragma unroll
        for (int s = 0; s < 4; ++s) {
            bestA[rowid[s]] = best[s]; idxA[rowid[s]] = bidx[s]; b2A[rowid[s]] = bsec[s];
        }
    }
    __syncthreads();
    if (wn == 1 && (lane & 3) == 0) {
        #pragma unroll
        for (int s = 0; s < 4; ++s) {
            float a1 = bestA[rowid[s]], a2 = b2A[rowid[s]]; int ai = idxA[rowid[s]];
            float c1 = best[s], c2 = bsec[s]; int ci = bidx[s];
            float nb1, nb2; int ni1;
            if (c1 < a1 || (c1 == a1 && ci < ai)) { nb1 = c1; ni1 = ci; nb2 = fminf(a1, c2); }
            else { nb1 = a1; ni1 = ai; nb2 = fminf(a2, c1); }
            int row = rbase + rowid[s];
            g_idx[row] = ni1;
            float margin = __fmaf_rn(nb1, 3e-7f, 3e-5f);
            if (!(nb2 - nb1 > margin)) {
                int pos = atomicAdd(&g_cnt, 1);
                g_list[pos] = row;
            }
        }
    }
}

// ---- stage 2: exact f32x2-FFMA full-scan GEMM over gathered flagged rows ----
// 64-row gathered tiles, 256 threads (8 warps), thread tile 4r x 8c — R1's proven shape.
#define XTM 64
#define XTN 128
__global__ __launch_bounds__(256)
void k_exact_gemm(const float* __restrict__ z, const float* __restrict__ emb) {
    extern __shared__ char smx[];
    float* zs   = (float*)smx;                    // [128k][64r]      32 KB
    float* es   = zs + DIM * XTM;                 // [128k][128c] swz 64 KB
    float* tall = es + DIM * XTN;                 // [2048]            8 KB
    float* ss   = tall + KCODES;                  // [64]

    const int tid = threadIdx.x;
    const int cnt = g_cnt;

    for (int i = tid; i < KCODES / 4; i += 256)
        ((float4*)tall)[i] = ((const float4*)g_t)[i];

    const int tc = tid & 15;   // codes {4tc..4tc+3} U {64+4tc..+3} per chunk
    const int tr = tid >> 4;   // rows 4tr..4tr+3

    for (int base = blockIdx.x * XTM; base < cnt; base += gridDim.x * XTM) {
        __syncthreads();   // previous tile fully done (zs/es reuse)

        // gather z rows (clamped duplicates in the tail), transpose k-major
        for (int i = tid; i < XTM * (DIM / 4); i += 256) {
            int r  = i & (XTM - 1);
            int k4 = i >> 6;
            int row = g_list[min(base + r, cnt - 1)];
            float4 v = *(const float4*)(z + (size_t)row * DIM + k4 * 4);
            zs[(k4 * 4 + 0) * XTM + r] = v.x;
            zs[(k4 * 4 + 1) * XTM + r] = v.y;
            zs[(k4 * 4 + 2) * XTM + r] = v.z;
            zs[(k4 * 4 + 3) * XTM + r] = v.w;
        }
        __syncthreads();

        if (tid < XTM) {
            float s = 0.f;
            #pragma unroll 8
            for (int k = 0; k < DIM; ++k) {
                float v = zs[k * XTM + tid];
                s = __fadd_rn(s, __fmul_rn(v, v));
            }
            ss[tid] = s;
        }
        __syncthreads();

        float s_r[4];
        #pragma unroll
        for (int r = 0; r < 4; ++r) s_r[r] = ss[tr * 4 + r];

        float best[4]; int bidx[4];
        #pragma unroll
        for (int r = 0; r < 4; ++r) { best[r] = CUDART_INF_F; bidx[r] = 0; }

        for (int ch = 0; ch < KCODES / XTN; ++ch) {
            const int cbase = ch * XTN;
            __syncthreads();
            // e chunk: coalesced read (warp per code row), group-swizzled STS
            #pragma unroll
            for (int it = 0; it < XTN / 8; ++it) {
                int cl = it * 8 + (tid >> 5);
                int k4 = tid & 31;
                float4 v = *(const float4*)(emb + (size_t)(cbase + cl) * DIM + k4 * 4);
                int g = cl >> 2, off = cl & 3;
                #pragma unroll
                for (int j = 0; j < 4; ++j) {
                    int k = k4 * 4 + j;
                    es[k * XTN + (((g ^ (k >> 2)) << 2) | off)] = ((const float*)&v)[j];
                }
            }
            __syncthreads();

            unsigned long long acc[16];
            #pragma unroll
            for (int i = 0; i < 16; ++i) acc[i] = 0ull;

            #pragma unroll 4
            for (int k = 0; k < DIM; ++k) {
                const float* ek = es + k * XTN;
                const int sw = k >> 2;
                ulonglong2 eA = *(const ulonglong2*)(ek + ((tc ^ sw) << 2));
                ulonglong2 eB = *(const ulonglong2*)(ek + (((tc + 16) ^ sw) << 2));
                float4 zv = *(const float4*)(zs + k * XTM + (tr << 2));
                unsigned long long z0 = pack2(zv.x), z1 = pack2(zv.y),
                                   z2 = pack2(zv.z), z3 = pack2(zv.w);
                FMA2(acc[0],  z0, eA.x); FMA2(acc[1],  z0, eA.y);
                FMA2(acc[2],  z0, eB.x); FMA2(acc[3],  z0, eB.y);
                FMA2(acc[4],  z1, eA.x); FMA2(acc[5],  z1, eA.y);
                FMA2(acc[6],  z1, eB.x); FMA2(acc[7],  z1, eB.y);
                FMA2(acc[8],  z2, eA.x); FMA2(acc[9],  z2, eA.y);
                FMA2(acc[10], z2, eB.x); FMA2(acc[11], z2, eB.y);
                FMA2(acc[12], z3, eA.x); FMA2(acc[13], z3, eA.y);
                FMA2(acc[14], z3, eB.x); FMA2(acc[15], z3, eB.y);
            }

            // dist = fl(fl(s - 2m) + t); ascending codes; strict <
            #pragma unroll
            for (int r = 0; r < 4; ++r) {
                #pragma unroll
                for (int p = 0; p < 4; ++p) {
                    float mlo, mhi;
                    unpack2(acc[r * 4 + p], mlo, mhi);
                    int clocal = (p < 2) ? (tc * 4 + p * 2) : (64 + tc * 4 + (p - 2) * 2);
                    int c0 = cbase + clocal;
                    float d0 = __fadd_rn(__fsub_rn(s_r[r], __fmul_rn(2.f, mlo)), tall[c0]);
                    float d1 = __fadd_rn(__fsub_rn(s_r[r], __fmul_rn(2.f, mhi)), tall[c0 + 1]);
                    if (d0 < best[r]) { best[r] = d0; bidx[r] = c0; }
                    if (d1 < best[r]) { best[r] = d1; bidx[r] = c0 + 1; }
                }
            }
        }

        // 16-lane (tc group) reduce, tie -> lowest index; write valid rows
        #pragma unroll
        for (int r = 0; r < 4; ++r) {
            float v = best[r]; int ix = bidx[r];
            #pragma unroll
            for (int off = 8; off > 0; off >>= 1) {
                float v2 = __shfl_down_sync(0xffffffffu, v, off, 16);
                int   i2 = __shfl_down_sync(0xffffffffu, ix, off, 16);
                if (v2 < v || (v2 == v && i2 < ix)) { v = v2; ix = i2; }
            }
            int rl = tr * 4 + r;
            if (tc == 0 && base + rl < cnt)
                g_idx[g_list[base + rl]] = ix;
        }
    }
}

// ---- gather + straight-through + indices + loss partials ----
__global__ __launch_bounds__(256)
void k_out(const float* __restrict__ z, const float* __restrict__ emb,
           float* __restrict__ out, long long out_size) {
    __shared__ float red[256];
    const int tid = threadIdx.x;
    const long long row0 = (long long)blockIdx.x * 64;
    float lsum = 0.f;

    for (int i = tid; i < 64 * (DIM / 4); i += 256) {
        long long r  = row0 + (i >> 5);
        int       d4 = (i & 31) * 4;
        int idx = g_idx[r];
        float4 q  = *(const float4*)(emb + (size_t)idx * DIM + d4);
        long long gi = r * DIM + d4;
        float4 zz = *(const float4*)(z + gi);
        float4 o; float df;
        df = __fsub_rn(q.x, zz.x); o.x = __fadd_rn(zz.x, df); lsum += df * df;
        df = __fsub_rn(q.y, zz.y); o.y = __fadd_rn(zz.y, df); lsum += df * df;
        df = __fsub_rn(q.z, zz.z); o.z = __fadd_rn(zz.z, df); lsum += df * df;
        df = __fsub_rn(q.w, zz.w); o.w = __fadd_rn(zz.w, df); lsum += df * df;
        if (gi + 3 < out_size) *(float4*)(out + gi) = o;
    }

    if (tid < 64) {
        long long r  = row0 + tid;
        long long gi = (long long)NZ + r;
        if (gi < out_size) out[gi] = (float)g_idx[r];
    }

    red[tid] = lsum;
    __syncthreads();
    for (int s = 128; s > 0; s >>= 1) {
        if (tid < s) red[tid] += red[tid + s];
        __syncthreads();
    }
    if (tid == 0) g_part[blockIdx.x] = red[0];
}

// ---- deterministic final loss reduce ----
__global__ void k_final(float* __restrict__ out, long long out_size) {
    __shared__ float red[256];
    const int tid = threadIdx.x;
    float s = 0.f;
    for (int i = tid; i < 1024; i += 256) s += g_part[i];
    red[tid] = s;
    __syncthreads();
    for (int w = 128; w > 0; w >>= 1) {
        if (tid < w) red[tid] += red[tid + w];
        __syncthreads();
    }
    if (tid == 0) {
        float m = red[0] / (float)NZ;
        float loss = __fadd_rn(m, __fmul_rn(0.25f, m));
        long long li = (long long)NZ + NROWS;
        if (li < out_size) out[li] = loss;
    }
}

extern "C" void kernel_launch(void* const* d_in, const int* in_sizes, int n_in,
                              void* d_out, int out_size) {
    const float* z   = (const float*)d_in[0];
    const float* emb = (const float*)d_in[1];
    float* out = (float*)d_out;

    const int smem_x = DIM * XTM * 4 + DIM * XTN * 4 + KCODES * 4 + XTM * 4;
    cudaFuncSetAttribute(k_argmin_tc, cudaFuncAttributeMaxDynamicSharedMemorySize, SMEM_SZ);
    cudaFuncSetAttribute(k_exact_gemm, cudaFuncAttributeMaxDynamicSharedMemorySize, smem_x);

    k_embnorm<<<16, 128>>>(emb);
    k_split<<<(KCODES * DIM) / 256, 256>>>(emb);
    k_argmin_tc<<<NROWS / TILE_M, NTH, SMEM_SZ>>>(z);
    k_exact_gemm<<<256, 256, smem_x>>>(z, emb);
    k_out<<<NROWS / 64, 256>>>(z, emb, out, (long long)out_size);
    k_final<<<1, 256>>>(out, (long long)out_size);
}

// round 15
// speedup vs baseline: 1.5949x; 1.0938x over previous
#include <cuda_runtime.h>
#include <cuda_fp16.h>
#include <math_constants.h>
#include <cstdint>

#define DIM 128
#define KCODES 2048
#define NROWS 65536
#define NZ (NROWS * DIM)
#define TILE_M 128
#define CHUNK 64
#define CHUNKS 32
#define NTH 256

__device__ __align__(16) float g_t[KCODES];
__device__ int   g_idx[NROWS];
__device__ float g_part[1024];
__device__ __align__(16) __half g_bh[KCODES * DIM];   // fl16(2048*e)
__device__ int g_cnt;
__device__ int g_list[NROWS];

// ---- smem byte offsets (stage 1): ~106 KB -> 2 CTAs/SM ----
#define OFF_A    0
#define OFF_B    32768
#define BUFSZ    16384
#define OFF_TALL 98304
#define OFF_SROW 106496
#define OFF_BEST 107008
#define OFF_IDX  107520
#define OFF_B2   108032
#define SMEM_SZ  108544

// ---- PTX helpers ----
static __device__ __forceinline__ void ldsm4(uint32_t* r, uint32_t a) {
    asm volatile("ldmatrix.sync.aligned.m8n8.x4.shared.b16 {%0,%1,%2,%3}, [%4];"
                 : "=r"(r[0]), "=r"(r[1]), "=r"(r[2]), "=r"(r[3]) : "r"(a));
}
static __device__ __forceinline__ void mma16816(float* c, const uint32_t* a,
                                                uint32_t b0, uint32_t b1) {
    asm volatile("mma.sync.aligned.m16n8k16.row.col.f32.f16.f16.f32 "
                 "{%0,%1,%2,%3}, {%4,%5,%6,%7}, {%8,%9}, {%0,%1,%2,%3};"
                 : "+f"(c[0]), "+f"(c[1]), "+f"(c[2]), "+f"(c[3])
                 : "r"(a[0]), "r"(a[1]), "r"(a[2]), "r"(a[3]), "r"(b0), "r"(b1));
}
#define CP_ASYNC16(d, s) asm volatile("cp.async.ca.shared.global [%0], [%1], 16;" :: "r"(d), "l"(s))
#define CP_COMMIT() asm volatile("cp.async.commit_group;" ::: "memory")
#define CP_WAIT0()  asm volatile("cp.async.wait_group 0;" ::: "memory")
#define CP_WAIT1()  asm volatile("cp.async.wait_group 1;" ::: "memory")
#define CP_WAIT2()  asm volatile("cp.async.wait_group 2;" ::: "memory")

// ---- f32x2 helpers for exact-GEMM fixup ----
#define FMA2(d, a, b) asm("fma.rn.f32x2 %0, %1, %2, %0;" : "+l"(d) : "l"(a), "l"(b))
static __device__ __forceinline__ unsigned long long pack2(float x) {
    unsigned long long r;
    unsigned int u = __float_as_uint(x);
    asm("mov.b64 %0, {%1, %1};" : "=l"(r) : "r"(u));
    return r;
}
static __device__ __forceinline__ void unpack2(unsigned long long v, float& lo, float& hi) {
    unsigned int a, b;
    asm("mov.b64 {%0, %1}, %2;" : "=r"(a), "=r"(b) : "l"(v));
    lo = __uint_as_float(a);
    hi = __uint_as_float(b);
}

// ---- prep: ||e||^2, exact sequential fp32, coalesced; zero counter ----
__global__ __launch_bounds__(128)
void k_embnorm(const float* __restrict__ emb) {
    __shared__ float sm[128 * 33];
    const int tid = threadIdx.x;
    const int cb = blockIdx.x * 128;
    if (blockIdx.x == 0 && tid == 0) g_cnt = 0;
    float s = 0.f;
    for (int kc = 0; kc < 4; ++kc) {
        __syncthreads();
        for (int i = tid; i < 128 * 32; i += 128) {
            int cl = i >> 5, kk = i & 31;
            sm[cl * 33 + kk] = emb[(size_t)(cb + cl) * DIM + kc * 32 + kk];
        }
        __syncthreads();
        #pragma unroll 8
        for (int kk = 0; kk < 32; ++kk) {
            float v = sm[tid * 33 + kk];
            s = __fadd_rn(s, __fmul_rn(v, v));
        }
    }
    g_t[cb + tid] = s;
}

// ---- prep: f16 codebook scaled by 2048 (exact power of 2) ----
__global__ void k_split(const float* __restrict__ emb) {
    int idx = blockIdx.x * blockDim.x + threadIdx.x;
    g_bh[idx] = __float2half_rn(__fmul_rn(emb[idx], 2048.0f));
}

// ---- B-chunk async fill ----
static __device__ __forceinline__ void fill_async(uint32_t bBase, int chunk, int tid) {
    const char* src = (const char*)g_bh + (size_t)chunk * CHUNK * 256;
    #pragma unroll
    for (int j = 0; j < 4; ++j) {
        int i = tid + j * NTH;
        int code = i >> 4;
        int kg = i & 15;
        uint32_t d = bBase + (uint32_t)(code * 256 + (((kg & ~7) | ((kg ^ code) & 7)) << 4));
        CP_ASYNC16(d, src + code * 256 + kg * 16);
    }
    CP_COMMIT();
}

// ---- stage 1: pure-f16 HMMA GEMM (K=128) + argmin + top-2 margin flag ----
__global__ __launch_bounds__(NTH, 2)
void k_argmin_tc(const float* __restrict__ z) {
    extern __shared__ char smc[];
    uint32_t sb;
    asm("{ .reg .u64 t; cvta.to.shared.u64 t, %1; cvt.u32.u64 %0, t; }" : "=r"(sb) : "l"(smc));
    float* tall  = (float*)(smc + OFF_TALL);
    float* srow  = (float*)(smc + OFF_SROW);
    float* bestA = (float*)(smc + OFF_BEST);
    int*   idxA  = (int*)(smc + OFF_IDX);
    float* b2A   = (float*)(smc + OFF_B2);

    const int tid = threadIdx.x;
    const int lane = tid & 31, wid = tid >> 5;
    const int wm = wid & 3, wn = wid >> 2;
    const int rbase = blockIdx.x * TILE_M;

    fill_async(sb + OFF_B + 0 * BUFSZ, 0, tid);
    fill_async(sb + OFF_B + 1 * BUFSZ, 1, tid);
    fill_async(sb + OFF_B + 2 * BUFSZ, 2, tid);

    for (int i = tid; i < KCODES / 4; i += NTH)
        ((float4*)tall)[i] = ((const float4*)g_t)[i];

    {
        int r = tid >> 1, half = tid & 1;
        const float* zr = z + (size_t)(rbase + r) * DIM + half * 64;
        char* arow = smc + OFF_A + r * 256;
        int rx = r & 7;
        #pragma unroll
        for (int g = 0; g < 8; ++g) {
            float4 v0 = *(const float4*)(zr + g * 8);
            float4 v1 = *(const float4*)(zr + g * 8 + 4);
            float f[8] = {v0.x, v0.y, v0.z, v0.w, v1.x, v1.y, v1.z, v1.w};
            uint32_t hp[4];
            #pragma unroll
            for (int e = 0; e < 4; ++e) {
                __half a = __float2half_rn(f[2 * e]);
                __half b = __float2half_rn(f[2 * e + 1]);
                hp[e] = (uint32_t)__half_as_ushort(a) | ((uint32_t)__half_as_ushort(b) << 16);
            }
            int kg0 = half * 8 + g;
            int ks0 = (kg0 & ~7) | ((kg0 & 7) ^ rx);
            *(uint4*)(arow + ks0 * 16) = *(uint4*)hp;
        }
    }

    if (tid < TILE_M) {
        const float* zr = z + (size_t)(rbase + tid) * DIM;
        float s = 0.f;
        #pragma unroll 8
        for (int k = 0; k < DIM; ++k)
            s = __fadd_rn(s, __fmul_rn(zr[k], zr[k]));
        srow[tid] = s;
    }
    __syncthreads();

    const int rx7 = lane & 7;
    const int klane = (lane >> 4) & 1;
    const uint32_t aRow0 = sb + OFF_A +
        (uint32_t)((wm * 32 + (lane & 7) + ((lane & 8) ? 8 : 0)) * 256);
    const uint32_t bRowOff =
        (uint32_t)((wn * 32 + (lane & 7) + ((lane & 8) ? 8 : 0)) * 256);

    float s_r[4]; int rowid[4];
    #pragma unroll
    for (int mi = 0; mi < 2; ++mi)
        #pragma unroll
        for (int h = 0; h < 2; ++h) {
            int rr = wm * 32 + mi * 16 + (lane >> 2) + 8 * h;
            rowid[mi * 2 + h] = rr;
            s_r[mi * 2 + h] = srow[rr];
        }
    float best[4], bsec[4]; int bidx[4];
    #pragma unroll
    for (int s = 0; s < 4; ++s) { best[s] = CUDART_INF_F; bsec[s] = CUDART_INF_F; bidx[s] = 0; }

    for (int c = 0; c < CHUNKS; ++c) {
        if (c < CHUNKS - 2) CP_WAIT2(); else if (c == CHUNKS - 2) CP_WAIT1(); else CP_WAIT0();
        __syncthreads();
        if (c + 3 < CHUNKS)
            fill_async(sb + OFF_B + ((c + 3) & 3) * BUFSZ, c + 3, tid);
        const uint32_t bBase = sb + OFF_B + (c & 3) * BUFSZ;

        float acc[2][4][4];
        #pragma unroll
        for (int i = 0; i < 32; ++i) ((float*)acc)[i] = 0.f;

        #pragma unroll
        for (int ks = 0; ks < 8; ++ks) {
            const int C = ks * 2 + klane;
            const uint32_t slot = (uint32_t)(((C & ~7) | ((C & 7) ^ rx7)) << 4);
            uint32_t A0[4], A1[4], B0[4], B1[4];
            ldsm4(A0, aRow0 + slot);
            ldsm4(A1, aRow0 + 16 * 256 + slot);
            ldsm4(B0, bBase + bRowOff + slot);
            ldsm4(B1, bBase + bRowOff + 16 * 256 + slot);
            mma16816(acc[0][0], A0, B0[0], B0[2]);
            mma16816(acc[0][1], A0, B0[1], B0[3]);
            mma16816(acc[0][2], A0, B1[0], B1[2]);
            mma16816(acc[0][3], A0, B1[1], B1[3]);
            mma16816(acc[1][0], A1, B0[0], B0[2]);
            mma16816(acc[1][1], A1, B0[1], B0[3]);
            mma16816(acc[1][2], A1, B1[0], B1[2]);
            mma16816(acc[1][3], A1, B1[1], B1[3]);
        }

        const int cb0 = c * CHUNK + wn * 32 + 2 * (lane & 3);
        #pragma unroll
        for (int mi = 0; mi < 2; ++mi)
            #pragma unroll
            for (int ni = 0; ni < 4; ++ni) {
                const float* cc = acc[mi][ni];
                int code = cb0 + ni * 8;
                float t0 = tall[code], t1 = tall[code + 1];
                #pragma unroll
                for (int h = 0; h < 2; ++h) {
                    int s = mi * 2 + h;
                    float d0 = __fadd_rn(__fsub_rn(s_r[s], __fmul_rn(cc[2 * h],     9.765625e-4f)), t0);
                    float d1 = __fadd_rn(__fsub_rn(s_r[s], __fmul_rn(cc[2 * h + 1], 9.765625e-4f)), t1);
                    if (d0 < best[s]) { bsec[s] = best[s]; best[s] = d0; bidx[s] = code; }
                    else if (d0 < bsec[s]) bsec[s] = d0;
                    if (d1 < best[s]) { bsec[s] = best[s]; best[s] = d1; bidx[s] = code + 1; }
                    else if (d1 < bsec[s]) bsec[s] = d1;
                }
            }
    }

    #pragma unroll
    for (int s = 0; s < 4; ++s) {
        float v = best[s], v2 = bsec[s]; int ix = bidx[s];
        #pragma unroll
        for (int off = 2; off > 0; off >>= 1) {
            float o1 = __shfl_down_sync(0xffffffffu, v, off, 4);
            int   oi = __shfl_down_sync(0xffffffffu, ix, off, 4);
            float o2 = __shfl_down_sync(0xffffffffu, v2, off, 4);
            if (o1 < v || (o1 == v && oi < ix)) { v2 = fminf(v, o2); v = o1; ix = oi; }
            else { v2 = fminf(v2, o1); }
        }
        best[s] = v; bsec[s] = v2; bidx[s] = ix;
    }
    if (wn == 0 && (lane & 3) == 0) {
        #pragma unroll
        for (int s = 0; s < 4; ++s) {
            bestA[rowid[s]] = best[s]; idxA[rowid[s]] = bidx[s]; b2A[rowid[s]] = bsec[s];
        }
    }
    __syncthreads();
    if (wn == 1 && (lane & 3) == 0) {
        #pragma unroll
        for (int s = 0; s < 4; ++s) {
            float a1 = bestA[rowid[s]], a2 = b2A[rowid[s]]; int ai = idxA[rowid[s]];
            float c1 = best[s], c2 = bsec[s]; int ci = bidx[s];
            float nb1, nb2; int ni1;
            if (c1 < a1 || (c1 == a1 && ci < ai)) { nb1 = c1; ni1 = ci; nb2 = fminf(a1, c2); }
            else { nb1 = a1; ni1 = ai; nb2 = fminf(a2, c1); }
            int row = rbase + rowid[s];
            g_idx[row] = ni1;
            float margin = __fmaf_rn(nb1, 3e-7f, 3e-5f);
            if (!(nb2 - nb1 > margin)) {
                int pos = atomicAdd(&g_cnt, 1);
                g_list[pos] = row;
            }
        }
    }
}

// ---- stage 2: exact f32x2-FFMA full-scan GEMM over gathered flagged rows ----
// 32-row gathered tiles (more CTAs, 2 CTAs/SM), 256 threads, thread tile 2r x 8c.
#define XTM 32
#define XTN 128
__global__ __launch_bounds__(256, 2)
void k_exact_gemm(const float* __restrict__ z, const float* __restrict__ emb) {
    extern __shared__ char smx[];
    float* zs   = (float*)smx;                    // [128k][32r]      16 KB
    float* es   = zs + DIM * XTM;                 // [128k][128c] swz 64 KB
    float* tall = es + DIM * XTN;                 // [2048]            8 KB
    float* ss   = tall + KCODES;                  // [32]

    const int tid = threadIdx.x;
    const int cnt = g_cnt;

    for (int i = tid; i < KCODES / 4; i += 256)
        ((float4*)tall)[i] = ((const float4*)g_t)[i];

    const int tc = tid & 15;   // codes {4tc..4tc+3} U {64+4tc..+3} per chunk
    const int tr = tid >> 4;   // rows 2tr, 2tr+1

    for (int base = blockIdx.x * XTM; base < cnt; base += gridDim.x * XTM) {
        __syncthreads();   // previous tile fully done (zs/es reuse)

        // gather z rows (clamped duplicates in the tail), transpose k-major
        for (int i = tid; i < XTM * (DIM / 4); i += 256) {
            int r  = i & (XTM - 1);
            int k4 = i >> 5;
            int row = g_list[min(base + r, cnt - 1)];
            float4 v = *(const float4*)(z + (size_t)row * DIM + k4 * 4);
            zs[(k4 * 4 + 0) * XTM + r] = v.x;
            zs[(k4 * 4 + 1) * XTM + r] = v.y;
            zs[(k4 * 4 + 2) * XTM + r] = v.z;
            zs[(k4 * 4 + 3) * XTM + r] = v.w;
        }
        __syncthreads();

        if (tid < XTM) {
            float s = 0.f;
            #pragma unroll 8
            for (int k = 0; k < DIM; ++k) {
                float v = zs[k * XTM + tid];
                s = __fadd_rn(s, __fmul_rn(v, v));
            }
            ss[tid] = s;
        }
        __syncthreads();

        float s_r[2];
        s_r[0] = ss[tr * 2];
        s_r[1] = ss[tr * 2 + 1];

        float best[2]; int bidx[2];
        best[0] = CUDART_INF_F; best[1] = CUDART_INF_F; bidx[0] = 0; bidx[1] = 0;

        for (int ch = 0; ch < KCODES / XTN; ++ch) {
            const int cbase = ch * XTN;
            __syncthreads();
            // e chunk: coalesced read (warp per code row), group-swizzled STS
            #pragma unroll
            for (int it = 0; it < XTN / 8; ++it) {
                int cl = it * 8 + (tid >> 5);
                int k4 = tid & 31;
                float4 v = *(const float4*)(emb + (size_t)(cbase + cl) * DIM + k4 * 4);
                int g = cl >> 2, off = cl & 3;
                #pragma unroll
                for (int j = 0; j < 4; ++j) {
                    int k = k4 * 4 + j;
                    es[k * XTN + (((g ^ (k >> 2)) << 2) | off)] = ((const float*)&v)[j];
                }
            }
            __syncthreads();

            unsigned long long acc[8];
            #pragma unroll
            for (int i = 0; i < 8; ++i) acc[i] = 0ull;

            #pragma unroll 4
            for (int k = 0; k < DIM; ++k) {
                const float* ek = es + k * XTN;
                const int sw = k >> 2;
                ulonglong2 eA = *(const ulonglong2*)(ek + ((tc ^ sw) << 2));
                ulonglong2 eB = *(const ulonglong2*)(ek + (((tc + 16) ^ sw) << 2));
                float2 zv = *(const float2*)(zs + k * XTM + (tr << 1));
                unsigned long long z0 = pack2(zv.x), z1 = pack2(zv.y);
                FMA2(acc[0], z0, eA.x); FMA2(acc[1], z0, eA.y);
                FMA2(acc[2], z0, eB.x); FMA2(acc[3], z0, eB.y);
                FMA2(acc[4], z1, eA.x); FMA2(acc[5], z1, eA.y);
                FMA2(acc[6], z1, eB.x); FMA2(acc[7], z1, eB.y);
            }

            // dist = fl(fl(s - 2m) + t); ascending codes; strict <
            #pragma unroll
            for (int r = 0; r < 2; ++r) {
                #pragma unroll
                for (int p = 0; p < 4; ++p) {
                    float mlo, mhi;
                    unpack2(acc[r * 4 + p], mlo, mhi);
                    int clocal = (p < 2) ? (tc * 4 + p * 2) : (64 + tc * 4 + (p - 2) * 2);
                    int c0 = cbase + clocal;
                    float d0 = __fadd_rn(__fsub_rn(s_r[r], __fmul_rn(2.f, mlo)), tall[c0]);
                    float d1 = __fadd_rn(__fsub_rn(s_r[r], __fmul_rn(2.f, mhi)), tall[c0 + 1]);
                    if (d0 < best[r]) { best[r] = d0; bidx[r] = c0; }
                    if (d1 < best[r]) { best[r] = d1; bidx[r] = c0 + 1; }
                }
            }
        }

        // 16-lane (tc group) reduce, tie -> lowest index; write valid rows
        #pragma unroll
        for (int r = 0; r < 2; ++r) {
            float v = best[r]; int ix = bidx[r];
            #pragma unroll
            for (int off = 8; off > 0; off >>= 1) {
                float v2 = __shfl_down_sync(0xffffffffu, v, off, 16);
                int   i2 = __shfl_down_sync(0xffffffffu, ix, off, 16);
                if (v2 < v || (v2 == v && i2 < ix)) { v = v2; ix = i2; }
            }
            int rl = tr * 2 + r;
            if (tc == 0 && base + rl < cnt)
                g_idx[g_list[base + rl]] = ix;
        }
    }
}

// ---- gather + straight-through + indices + loss partials ----
__global__ __launch_bounds__(256)
void k_out(const float* __restrict__ z, const float* __restrict__ emb,
           float* __restrict__ out, long long out_size) {
    __shared__ float red[256];
    const int tid = threadIdx.x;
    const long long row0 = (long long)blockIdx.x * 64;
    float lsum = 0.f;

    for (int i = tid; i < 64 * (DIM / 4); i += 256) {
        long long r  = row0 + (i >> 5);
        int       d4 = (i & 31) * 4;
        int idx = g_idx[r];
        float4 q  = *(const float4*)(emb + (size_t)idx * DIM + d4);
        long long gi = r * DIM + d4;
        float4 zz = *(const float4*)(z + gi);
        float4 o; float df;
        df = __fsub_rn(q.x, zz.x); o.x = __fadd_rn(zz.x, df); lsum += df * df;
        df = __fsub_rn(q.y, zz.y); o.y = __fadd_rn(zz.y, df); lsum += df * df;
        df = __fsub_rn(q.z, zz.z); o.z = __fadd_rn(zz.z, df); lsum += df * df;
        df = __fsub_rn(q.w, zz.w); o.w = __fadd_rn(zz.w, df); lsum += df * df;
        if (gi + 3 < out_size) *(float4*)(out + gi) = o;
    }

    if (tid < 64) {
        long long r  = row0 + tid;
        long long gi = (long long)NZ + r;
        if (gi < out_size) out[gi] = (float)g_idx[r];
    }

    red[tid] = lsum;
    __syncthreads();
    for (int s = 128; s > 0; s >>= 1) {
        if (tid < s) red[tid] += red[tid + s];
        __syncthreads();
    }
    if (tid == 0) g_part[blockIdx.x] = red[0];
}

// ---- deterministic final loss reduce ----
__global__ void k_final(float* __restrict__ out, long long out_size) {
    __shared__ float red[256];
    const int tid = threadIdx.x;
    float s = 0.f;
    for (int i = tid; i < 1024; i += 256) s += g_part[i];
    red[tid] = s;
    __syncthreads();
    for (int w = 128; w > 0; w >>= 1) {
        if (tid < w) red[tid] += red[tid + w];
        __syncthreads();
    }
    if (tid == 0) {
        float m = red[0] / (float)NZ;
        float loss = __fadd_rn(m, __fmul_rn(0.25f, m));
        long long li = (long long)NZ + NROWS;
        if (li < out_size) out[li] = loss;
    }
}

extern "C" void kernel_launch(void* const* d_in, const int* in_sizes, int n_in,
                              void* d_out, int out_size) {
    const float* z   = (const float*)d_in[0];
    const float* emb = (const float*)d_in[1];
    float* out = (float*)d_out;

    const int smem_x = DIM * XTM * 4 + DIM * XTN * 4 + KCODES * 4 + XTM * 4;
    cudaFuncSetAttribute(k_argmin_tc, cudaFuncAttributeMaxDynamicSharedMemorySize, SMEM_SZ);
    cudaFuncSetAttribute(k_exact_gemm, cudaFuncAttributeMaxDynamicSharedMemorySize, smem_x);

    k_embnorm<<<16, 128>>>(emb);
    k_split<<<(KCODES * DIM) / 256, 256>>>(emb);
    k_argmin_tc<<<NROWS / TILE_M, NTH, SMEM_SZ>>>(z);
    k_exact_gemm<<<512, 256, smem_x>>>(z, emb);
    k_out<<<NROWS / 64, 256>>>(z, emb, out, (long long)out_size);
    k_final<<<1, 256>>>(out, (long long)out_size);
}